// round 3
// baseline (speedup 1.0000x reference)
#include <cuda_runtime.h>
#include <cuda_bf16.h>
#include <cstdint>

#define VOCAB 10000
#define EMBD 100
#define EMBP 104      // EMB padded to multiple of 8 for bf16 MMA k-tiles
#define SEQ 80
#define UNITS 512
#define BATCH 2048
#define BT (BATCH*SEQ)   // 163840

#define KC 32            // K-chunk per SMEM stage
#define PA 8             // A smem row pad (bf16 elems) -> 80B rows, LDSM conflict-free
#define PB 8             // B smem row pad

// ---------------- device scratch (static, no allocations) ----------------
__device__ __nv_bfloat16 g_X0[(size_t)BT * EMBP];     // embedded input, padded
__device__ __nv_bfloat16 g_X [(size_t)BT * UNITS];    // current layer activations [B,T,H]
__device__ float         g_XW[(size_t)BT * UNITS];    // per-layer input projection (fp32)
__device__ __nv_bfloat16 g_W1b[EMBP * UNITS];         // W1 padded, bf16
__device__ __nv_bfloat16 g_Wb [3][UNITS * UNITS];     // W2..W4 bf16
__device__ __nv_bfloat16 g_Ub [4][UNITS * UNITS];     // U1..U4 bf16

// ---------------- small helper kernels ----------------
__global__ void cvt_kernel(const float* __restrict__ s, __nv_bfloat16* __restrict__ d, int n) {
    int i = blockIdx.x * blockDim.x + threadIdx.x;
    if (i < n) d[i] = __float2bfloat16(s[i]);
}

__global__ void padw1_kernel(const float* __restrict__ W1, __nv_bfloat16* __restrict__ d) {
    int i = blockIdx.x * blockDim.x + threadIdx.x;
    if (i >= EMBP * UNITS) return;
    int r = i / UNITS, c = i - r * UNITS;
    d[i] = __float2bfloat16(r < EMBD ? W1[r * UNITS + c] : 0.0f);
}

__global__ void embed_kernel(const int* __restrict__ tokens, const float* __restrict__ emb,
                             __nv_bfloat16* __restrict__ X0) {
    int i = blockIdx.x * blockDim.x + threadIdx.x;
    if (i >= BT * EMBP) return;
    int row = i / EMBP, k = i - row * EMBP;
    int tok = tokens[row];
    float v = (k < EMBD) ? emb[(size_t)tok * EMBD + k] : 0.0f;
    X0[i] = __float2bfloat16(v);
}

// ---------------- PTX helpers ----------------
__device__ __forceinline__ uint32_t smaddr(const void* p) {
    return (uint32_t)__cvta_generic_to_shared(p);
}
__device__ __forceinline__ void cpasync16(void* dst_smem, const void* src_g, int srcsz) {
    asm volatile("cp.async.cg.shared.global [%0], [%1], 16, %2;\n"
                 :: "r"(smaddr(dst_smem)), "l"(src_g), "r"(srcsz));
}
__device__ __forceinline__ void cp_commit() { asm volatile("cp.async.commit_group;\n"); }
__device__ __forceinline__ void cp_wait1()  { asm volatile("cp.async.wait_group 1;\n"); }

__device__ __forceinline__ void ldsm4(uint32_t (&r)[4], uint32_t addr) {
    asm volatile("ldmatrix.sync.aligned.m8n8.x4.shared.b16 {%0,%1,%2,%3}, [%4];\n"
                 : "=r"(r[0]), "=r"(r[1]), "=r"(r[2]), "=r"(r[3]) : "r"(addr));
}
__device__ __forceinline__ void ldsm4t(uint32_t (&r)[4], uint32_t addr) {
    asm volatile("ldmatrix.sync.aligned.m8n8.x4.trans.shared.b16 {%0,%1,%2,%3}, [%4];\n"
                 : "=r"(r[0]), "=r"(r[1]), "=r"(r[2]), "=r"(r[3]) : "r"(addr));
}
__device__ __forceinline__ void mma16816(float (&d)[4], const uint32_t (&a)[4],
                                         uint32_t b0, uint32_t b1) {
    asm volatile("mma.sync.aligned.m16n8k16.row.col.f32.bf16.bf16.f32 "
                 "{%0,%1,%2,%3}, {%4,%5,%6,%7}, {%8,%9}, {%0,%1,%2,%3};\n"
                 : "+f"(d[0]), "+f"(d[1]), "+f"(d[2]), "+f"(d[3])
                 : "r"(a[0]), "r"(a[1]), "r"(a[2]), "r"(a[3]), "r"(b0), "r"(b1));
}

// ---------------- GEMM: C[M,N] = A[M,K] @ Bw[K,N]  (bf16 MMA, fp32 acc) ----------------
// MODE 0: Cf[row*ldo + c] = acc + bias[c]               (fp32 store)
// MODE 1: Cb[row*ldo + c] = tanh(acc + XW[row*ldo + c]) (bf16 store)
// BM = 128 fixed, 256 threads = 8 warps (4 along M x 2 along N).
template<int BN, int MODE>
__global__ __launch_bounds__(256) void gemm_bf16(
    const __nv_bfloat16* __restrict__ A, long lda,
    const __nv_bfloat16* __restrict__ Bw, int K,
    const float* __restrict__ bias,
    float* __restrict__ Cf,
    const float* __restrict__ XW,
    __nv_bfloat16* __restrict__ Cb,
    long ldo, int skipA)
{
    constexpr int WC  = BN / 2;   // warp tile cols
    constexpr int NT8 = WC / 8;   // 8-wide n-tiles per warp

    __shared__ __align__(16) __nv_bfloat16 As[2][128][KC + PA];
    __shared__ __align__(16) __nv_bfloat16 Bs[2][KC][BN + PB];

    const int tid  = threadIdx.x;
    const int lane = tid & 31;
    const int wid  = tid >> 5;
    const int wm   = wid & 3;
    const int wn   = wid >> 2;

    const int rowBase = blockIdx.y * 128;
    const int colBase = blockIdx.x * BN;

    const int nstages = (K + KC - 1) / KC;

    auto load_stage = [&](int s, int kbase) {
        // A tile: 128 x KC bf16 -> 512 x 16B, 2 per thread
        #pragma unroll
        for (int i = 0; i < 2; i++) {
            int lin = tid + i * 256;
            int row = lin >> 2;
            int c4  = lin & 3;
            int k   = kbase + c4 * 8;
            int kc  = (k + 8 <= K) ? k : (K - 8);             // clamp for safe addr
            const void* src = A + (size_t)(rowBase + row) * lda + kc;
            int sz = (!skipA && (k + 8 <= K)) ? 16 : 0;       // 0 => zero-fill
            cpasync16(&As[s][row][c4 * 8], src, sz);
        }
        // B tile: KC x BN bf16 -> 4*BN x 16B
        #pragma unroll
        for (int i = 0; i < (4 * BN) / 256; i++) {
            int lin = tid + i * 256;
            int kr  = lin / (BN / 8);
            int n8  = lin % (BN / 8);
            int krow = kbase + kr;
            int krc  = (krow < K) ? krow : (K - 1);
            const void* src = Bw + (size_t)krc * UNITS + colBase + n8 * 8;
            int sz = (krow < K) ? 16 : 0;
            cpasync16(&Bs[s][kr][n8 * 8], src, sz);
        }
    };

    float acc[2][NT8][4];
    #pragma unroll
    for (int mt = 0; mt < 2; mt++)
        #pragma unroll
        for (int nt = 0; nt < NT8; nt++)
            #pragma unroll
            for (int j = 0; j < 4; j++) acc[mt][nt][j] = 0.0f;

    load_stage(0, 0);
    cp_commit();

    for (int st = 0; st < nstages; ++st) {
        if (st + 1 < nstages) load_stage((st + 1) & 1, (st + 1) * KC);
        cp_commit();
        cp_wait1();
        __syncthreads();
        const int buf = st & 1;

        #pragma unroll
        for (int kk = 0; kk < KC; kk += 16) {
            uint32_t a[2][4];
            #pragma unroll
            for (int mt = 0; mt < 2; mt++) {
                ldsm4(a[mt], smaddr(&As[buf][wm * 32 + mt * 16 + (lane & 15)]
                                       [kk + ((lane >> 4) << 3)]));
            }
            #pragma unroll
            for (int np = 0; np < NT8 / 2; np++) {
                uint32_t b[4];
                ldsm4t(b, smaddr(&Bs[buf][kk + (lane & 15)]
                                    [wn * WC + np * 16 + ((lane >> 4) << 3)]));
                mma16816(acc[0][2 * np],     a[0], b[0], b[1]);
                mma16816(acc[1][2 * np],     a[1], b[0], b[1]);
                mma16816(acc[0][2 * np + 1], a[0], b[2], b[3]);
                mma16816(acc[1][2 * np + 1], a[1], b[2], b[3]);
            }
        }
        __syncthreads();
    }

    // epilogue
    #pragma unroll
    for (int mt = 0; mt < 2; mt++) {
        #pragma unroll
        for (int nt = 0; nt < NT8; nt++) {
            int r0 = rowBase + wm * 32 + mt * 16 + (lane >> 2);
            int c  = colBase + wn * WC + nt * 8 + (lane & 3) * 2;
            if (MODE == 0) {
                float b0v = bias[c], b1v = bias[c + 1];
                float2 v0 = make_float2(acc[mt][nt][0] + b0v, acc[mt][nt][1] + b1v);
                float2 v1 = make_float2(acc[mt][nt][2] + b0v, acc[mt][nt][3] + b1v);
                *(float2*)(Cf + (size_t)r0 * ldo + c)       = v0;
                *(float2*)(Cf + (size_t)(r0 + 8) * ldo + c) = v1;
            } else {
                float2 x0 = *(const float2*)(XW + (size_t)r0 * ldo + c);
                float2 x1 = *(const float2*)(XW + (size_t)(r0 + 8) * ldo + c);
                float2 o0 = make_float2(tanhf(acc[mt][nt][0] + x0.x),
                                        tanhf(acc[mt][nt][1] + x0.y));
                float2 o1 = make_float2(tanhf(acc[mt][nt][2] + x1.x),
                                        tanhf(acc[mt][nt][3] + x1.y));
                *(__nv_bfloat162*)(Cb + (size_t)r0 * ldo + c)       = __float22bfloat162_rn(o0);
                *(__nv_bfloat162*)(Cb + (size_t)(r0 + 8) * ldo + c) = __float22bfloat162_rn(o1);
            }
        }
    }
}

// ---------------- head: out[b] = sigmoid(h_last . Wo + bo) ----------------
__global__ void final_kernel(const __nv_bfloat16* __restrict__ X,
                             const float* __restrict__ Wo, const float* __restrict__ bo,
                             float* __restrict__ out) {
    int gw   = (blockIdx.x * blockDim.x + threadIdx.x) >> 5;
    int lane = threadIdx.x & 31;
    if (gw >= BATCH) return;
    const __nv_bfloat16* h = X + ((size_t)gw * SEQ + (SEQ - 1)) * UNITS;
    float s = 0.0f;
    for (int k = lane; k < UNITS; k += 32) s += __bfloat162float(h[k]) * Wo[k];
    #pragma unroll
    for (int o = 16; o; o >>= 1) s += __shfl_xor_sync(0xffffffffu, s, o);
    if (lane == 0) out[gw] = 1.0f / (1.0f + expf(-(s + bo[0])));
}

// ---------------- host ----------------
extern "C" void kernel_launch(void* const* d_in, const int* in_sizes, int n_in,
                              void* d_out, int out_size) {
    const int*   tokens = (const int*)d_in[0];
    const float* emb    = (const float*)d_in[1];
    const float* W[4]  = {(const float*)d_in[2], (const float*)d_in[5],
                          (const float*)d_in[8], (const float*)d_in[11]};
    const float* U[4]  = {(const float*)d_in[3], (const float*)d_in[6],
                          (const float*)d_in[9], (const float*)d_in[12]};
    const float* bv[4] = {(const float*)d_in[4], (const float*)d_in[7],
                          (const float*)d_in[10], (const float*)d_in[13]};
    const float* Wo = (const float*)d_in[14];
    const float* bo = (const float*)d_in[15];
    float* out = (float*)d_out;

    __nv_bfloat16 *X0p, *Xp, *W1bp, *Wbp, *Ubp;
    float* XWp;
    cudaGetSymbolAddress((void**)&X0p,  g_X0);
    cudaGetSymbolAddress((void**)&Xp,   g_X);
    cudaGetSymbolAddress((void**)&XWp,  g_XW);
    cudaGetSymbolAddress((void**)&W1bp, g_W1b);
    cudaGetSymbolAddress((void**)&Wbp,  g_Wb);
    cudaGetSymbolAddress((void**)&Ubp,  g_Ub);

    // weight conversions (cheap, deterministic, every call)
    padw1_kernel<<<(EMBP * UNITS + 255) / 256, 256>>>(W[0], W1bp);
    for (int l = 1; l < 4; l++)
        cvt_kernel<<<(UNITS * UNITS + 255) / 256, 256>>>(
            W[l], Wbp + (size_t)(l - 1) * UNITS * UNITS, UNITS * UNITS);
    for (int l = 0; l < 4; l++)
        cvt_kernel<<<(UNITS * UNITS + 255) / 256, 256>>>(
            U[l], Ubp + (size_t)l * UNITS * UNITS, UNITS * UNITS);

    // embedding gather (bf16, padded to EMBP)
    embed_kernel<<<(BT * EMBP + 255) / 256, 256>>>(tokens, emb, X0p);

    const long ldH = (long)SEQ * UNITS;

    for (int l = 0; l < 4; l++) {
        // parallel part: XW = X_in @ W_l + b_l   (one big GEMM over all B*T rows)
        if (l == 0) {
            gemm_bf16<128, 0><<<dim3(UNITS / 128, BT / 128), 256>>>(
                X0p, (long)EMBP, W1bp, EMBP, bv[0],
                XWp, nullptr, nullptr, (long)UNITS, 0);
        } else {
            gemm_bf16<128, 0><<<dim3(UNITS / 128, BT / 128), 256>>>(
                Xp, (long)UNITS, Wbp + (size_t)(l - 1) * UNITS * UNITS, UNITS, bv[l],
                XWp, nullptr, nullptr, (long)UNITS, 0);
        }
        // sequential part: h_t = tanh(XW_t + h_{t-1} @ U_l)
        for (int t = 0; t < SEQ; t++) {
            const __nv_bfloat16* Ap = (t == 0) ? Xp : (Xp + (size_t)(t - 1) * UNITS);
            gemm_bf16<64, 1><<<dim3(UNITS / 64, BATCH / 128), 256>>>(
                Ap, ldH, Ubp + (size_t)l * UNITS * UNITS, UNITS, nullptr,
                nullptr, XWp + (size_t)t * UNITS, Xp + (size_t)t * UNITS,
                ldH, (t == 0) ? 1 : 0);
        }
    }

    final_kernel<<<BATCH / 8, 256>>>(Xp, Wo, bo, out);
}

// round 4
// speedup vs baseline: 1.2460x; 1.2460x over previous
#include <cuda_runtime.h>
#include <cuda_bf16.h>
#include <cstdint>

#define VOCAB 10000
#define EMBD 100
#define EMBP 104      // EMB padded to multiple of 8 for bf16 MMA k-tiles
#define SEQ 80
#define UNITS 512
#define BATCH 2048
#define BT (BATCH*SEQ)   // 163840

#define KC 32            // K-chunk per SMEM stage (big GEMM)
#define PA 8             // A smem row pad
#define PB 8             // B smem row pad

// persistent recurrence kernel config
#define RBN 64           // N tile per CTA
#define RKC 64           // K chunk per stage
#define RPAD 8           // row pad (-> 72-elem rows, 144B, ldmatrix conflict-free)
#define RGRIDX (UNITS/RBN)    // 8
#define RGRIDY (BATCH/128)    // 16

// ---------------- device scratch (static, no allocations) ----------------
__device__ __nv_bfloat16 g_X0[(size_t)BT * EMBP];     // embedded input, padded
__device__ __nv_bfloat16 g_X [(size_t)BT * UNITS];    // current layer activations [B,T,H]
__device__ float         g_XW[(size_t)BT * UNITS];    // per-layer input projection (fp32)
__device__ __nv_bfloat16 g_W1b[EMBP * UNITS];         // W1 padded, bf16
__device__ __nv_bfloat16 g_Wb [3][UNITS * UNITS];     // W2..W4 bf16
__device__ __nv_bfloat16 g_Ub [4][UNITS * UNITS];     // U1..U4 bf16
__device__ unsigned      g_bar[4][RGRIDY][SEQ];       // per (layer,row-group,step) barrier

// ---------------- small helper kernels ----------------
__global__ void cvt_kernel(const float* __restrict__ s, __nv_bfloat16* __restrict__ d, int n) {
    int i = blockIdx.x * blockDim.x + threadIdx.x;
    if (i < n) d[i] = __float2bfloat16(s[i]);
}

__global__ void padw1_kernel(const float* __restrict__ W1, __nv_bfloat16* __restrict__ d) {
    int i = blockIdx.x * blockDim.x + threadIdx.x;
    if (i >= EMBP * UNITS) return;
    int r = i / UNITS, c = i - r * UNITS;
    d[i] = __float2bfloat16(r < EMBD ? W1[r * UNITS + c] : 0.0f);
}

__global__ void embed_kernel(const int* __restrict__ tokens, const float* __restrict__ emb,
                             __nv_bfloat16* __restrict__ X0) {
    int i = blockIdx.x * blockDim.x + threadIdx.x;
    if (i >= BT * EMBP) return;
    int row = i / EMBP, k = i - row * EMBP;
    int tok = tokens[row];
    float v = (k < EMBD) ? emb[(size_t)tok * EMBD + k] : 0.0f;
    X0[i] = __float2bfloat16(v);
}

__global__ void zero_bar_kernel() {
    int i = blockIdx.x * blockDim.x + threadIdx.x;
    if (i < 4 * RGRIDY * SEQ) ((unsigned*)g_bar)[i] = 0u;
}

// ---------------- PTX helpers ----------------
__device__ __forceinline__ uint32_t smaddr(const void* p) {
    return (uint32_t)__cvta_generic_to_shared(p);
}
__device__ __forceinline__ void cpasync16(void* dst_smem, const void* src_g, int srcsz) {
    asm volatile("cp.async.cg.shared.global [%0], [%1], 16, %2;\n"
                 :: "r"(smaddr(dst_smem)), "l"(src_g), "r"(srcsz));
}
__device__ __forceinline__ void cp_commit() { asm volatile("cp.async.commit_group;\n"); }
__device__ __forceinline__ void cp_wait1()  { asm volatile("cp.async.wait_group 1;\n"); }
__device__ __forceinline__ void cp_wait0()  { asm volatile("cp.async.wait_group 0;\n"); }

__device__ __forceinline__ void ldsm4(uint32_t (&r)[4], uint32_t addr) {
    asm volatile("ldmatrix.sync.aligned.m8n8.x4.shared.b16 {%0,%1,%2,%3}, [%4];\n"
                 : "=r"(r[0]), "=r"(r[1]), "=r"(r[2]), "=r"(r[3]) : "r"(addr));
}
__device__ __forceinline__ void ldsm4t(uint32_t (&r)[4], uint32_t addr) {
    asm volatile("ldmatrix.sync.aligned.m8n8.x4.trans.shared.b16 {%0,%1,%2,%3}, [%4];\n"
                 : "=r"(r[0]), "=r"(r[1]), "=r"(r[2]), "=r"(r[3]) : "r"(addr));
}
__device__ __forceinline__ void mma16816(float (&d)[4], const uint32_t (&a)[4],
                                         uint32_t b0, uint32_t b1) {
    asm volatile("mma.sync.aligned.m16n8k16.row.col.f32.bf16.bf16.f32 "
                 "{%0,%1,%2,%3}, {%4,%5,%6,%7}, {%8,%9}, {%0,%1,%2,%3};\n"
                 : "+f"(d[0]), "+f"(d[1]), "+f"(d[2]), "+f"(d[3])
                 : "r"(a[0]), "r"(a[1]), "r"(a[2]), "r"(a[3]), "r"(b0), "r"(b1));
}

// ---------------- big GEMM (XW projection): C[M,N] = A[M,K] @ Bw[K,N] + bias ----------------
// BM = 128 fixed, BN = 128, 256 threads = 8 warps (4 along M x 2 along N). fp32 store.
template<int BN>
__global__ __launch_bounds__(256) void gemm_bf16(
    const __nv_bfloat16* __restrict__ A, long lda,
    const __nv_bfloat16* __restrict__ Bw, int K,
    const float* __restrict__ bias,
    float* __restrict__ Cf, long ldo)
{
    constexpr int WC  = BN / 2;   // warp tile cols
    constexpr int NT8 = WC / 8;   // 8-wide n-tiles per warp

    __shared__ __align__(16) __nv_bfloat16 As[2][128][KC + PA];
    __shared__ __align__(16) __nv_bfloat16 Bs[2][KC][BN + PB];

    const int tid  = threadIdx.x;
    const int lane = tid & 31;
    const int wid  = tid >> 5;
    const int wm   = wid & 3;
    const int wn   = wid >> 2;

    const int rowBase = blockIdx.y * 128;
    const int colBase = blockIdx.x * BN;

    const int nstages = (K + KC - 1) / KC;

    auto load_stage = [&](int s, int kbase) {
        #pragma unroll
        for (int i = 0; i < 2; i++) {
            int lin = tid + i * 256;
            int row = lin >> 2;
            int c4  = lin & 3;
            int k   = kbase + c4 * 8;
            int kc  = (k + 8 <= K) ? k : (K - 8);
            const void* src = A + (size_t)(rowBase + row) * lda + kc;
            int sz = (k + 8 <= K) ? 16 : 0;
            cpasync16(&As[s][row][c4 * 8], src, sz);
        }
        #pragma unroll
        for (int i = 0; i < (4 * BN) / 256; i++) {
            int lin = tid + i * 256;
            int kr  = lin / (BN / 8);
            int n8  = lin % (BN / 8);
            int krow = kbase + kr;
            int krc  = (krow < K) ? krow : (K - 1);
            const void* src = Bw + (size_t)krc * UNITS + colBase + n8 * 8;
            int sz = (krow < K) ? 16 : 0;
            cpasync16(&Bs[s][kr][n8 * 8], src, sz);
        }
    };

    float acc[2][NT8][4];
    #pragma unroll
    for (int mt = 0; mt < 2; mt++)
        #pragma unroll
        for (int nt = 0; nt < NT8; nt++)
            #pragma unroll
            for (int j = 0; j < 4; j++) acc[mt][nt][j] = 0.0f;

    load_stage(0, 0);
    cp_commit();

    for (int st = 0; st < nstages; ++st) {
        if (st + 1 < nstages) load_stage((st + 1) & 1, (st + 1) * KC);
        cp_commit();
        cp_wait1();
        __syncthreads();
        const int buf = st & 1;

        #pragma unroll
        for (int kk = 0; kk < KC; kk += 16) {
            uint32_t a[2][4];
            #pragma unroll
            for (int mt = 0; mt < 2; mt++) {
                ldsm4(a[mt], smaddr(&As[buf][wm * 32 + mt * 16 + (lane & 15)]
                                       [kk + ((lane >> 4) << 3)]));
            }
            #pragma unroll
            for (int np = 0; np < NT8 / 2; np++) {
                uint32_t b[4];
                ldsm4t(b, smaddr(&Bs[buf][kk + (lane & 15)]
                                    [wn * WC + np * 16 + ((lane >> 4) << 3)]));
                mma16816(acc[0][2 * np],     a[0], b[0], b[1]);
                mma16816(acc[1][2 * np],     a[1], b[0], b[1]);
                mma16816(acc[0][2 * np + 1], a[0], b[2], b[3]);
                mma16816(acc[1][2 * np + 1], a[1], b[2], b[3]);
            }
        }
        __syncthreads();
    }

    #pragma unroll
    for (int mt = 0; mt < 2; mt++) {
        #pragma unroll
        for (int nt = 0; nt < NT8; nt++) {
            int r0 = rowBase + wm * 32 + mt * 16 + (lane >> 2);
            int c  = colBase + wn * WC + nt * 8 + (lane & 3) * 2;
            float b0v = bias[c], b1v = bias[c + 1];
            float2 v0 = make_float2(acc[mt][nt][0] + b0v, acc[mt][nt][1] + b1v);
            float2 v1 = make_float2(acc[mt][nt][2] + b0v, acc[mt][nt][3] + b1v);
            *(float2*)(Cf + (size_t)r0 * ldo + c)       = v0;
            *(float2*)(Cf + (size_t)(r0 + 8) * ldo + c) = v1;
        }
    }
}

// ---------------- persistent per-layer recurrence ----------------
// grid = (8, 16) = 128 CTAs, all co-resident (1 CTA/SM by smem). CTA (x,y):
// computes h rows [128y,128y+128) cols [64x,64x+64) for all 80 steps.
// U slice [512][64] cached in SMEM once. Row-group barrier of 8 CTAs per step.
#define RSMEM_BYTES ((512*(RBN+RPAD) + 2*128*(RKC+RPAD)) * 2)

__global__ __launch_bounds__(256, 1) void rnn_layer_kernel(
    const __nv_bfloat16* __restrict__ Uw,
    const float* __restrict__ XW,      // [B*T, UNITS] fp32, row = b*SEQ+t
    __nv_bfloat16* __restrict__ X,     // [B*T, UNITS] bf16 h storage (in/out)
    int layer)
{
    extern __shared__ __align__(16) unsigned char sraw[];
    __nv_bfloat16* Us = (__nv_bfloat16*)sraw;                 // [512][RBN+RPAD]
    __nv_bfloat16* As = Us + 512 * (RBN + RPAD);              // [2][128][RKC+RPAD]

    const int tid  = threadIdx.x;
    const int lane = tid & 31;
    const int wid  = tid >> 5;
    const int wm   = wid & 3;       // 4 warps along M (32 rows each)
    const int wn   = wid >> 2;      // 2 warps along N (32 cols each)
    const int colBase = blockIdx.x * RBN;
    const int rowBase = blockIdx.y * 128;

    // ---- load U slice [512][RBN] into SMEM (once) ----
    for (int i = tid; i < 512 * (RBN / 8); i += 256) {
        int r  = i >> 3;           // 0..511
        int c8 = i & 7;            // 8 chunks of 8 bf16
        cpasync16(Us + (size_t)r * (RBN + RPAD) + c8 * 8,
                  Uw + (size_t)r * UNITS + colBase + c8 * 8, 16);
    }
    cp_commit();
    cp_wait0();
    __syncthreads();

    unsigned* barRow = &g_bar[layer][blockIdx.y][0];

    for (int t = 0; t < SEQ; ++t) {
        float acc[2][4][4];
        #pragma unroll
        for (int mt = 0; mt < 2; mt++)
            #pragma unroll
            for (int nt = 0; nt < 4; nt++)
                #pragma unroll
                for (int j = 0; j < 4; j++) acc[mt][nt][j] = 0.0f;

        if (t > 0) {
            // A = h_{t-1} rows [rowBase, rowBase+128), all 512 cols
            const __nv_bfloat16* Abase = X + (size_t)(t - 1) * UNITS;
            auto loadA = [&](int s, int kbase) {
                #pragma unroll
                for (int i = 0; i < 4; i++) {
                    int lin = tid + i * 256;
                    int row = lin >> 3;    // 0..127
                    int c8  = lin & 7;     // 8 chunks of 8 bf16 (RKC=64)
                    cpasync16(As + ((size_t)s * 128 + row) * (RKC + RPAD) + c8 * 8,
                              Abase + (size_t)(rowBase + row) * (SEQ * UNITS)
                                    + kbase + c8 * 8, 16);
                }
            };

            loadA(0, 0);
            cp_commit();
            constexpr int NST = UNITS / RKC;   // 8
            #pragma unroll 1
            for (int st = 0; st < NST; ++st) {
                if (st + 1 < NST) loadA((st + 1) & 1, (st + 1) * RKC);
                cp_commit();
                cp_wait1();
                __syncthreads();
                const int buf = st & 1;

                #pragma unroll
                for (int kk = 0; kk < RKC; kk += 16) {
                    const int kg = st * RKC + kk;   // global k for U
                    uint32_t a[2][4];
                    #pragma unroll
                    for (int mt = 0; mt < 2; mt++) {
                        ldsm4(a[mt], smaddr(As + ((size_t)buf * 128 + wm * 32 + mt * 16
                                                  + (lane & 15)) * (RKC + RPAD)
                                                 + kk + ((lane >> 4) << 3)));
                    }
                    #pragma unroll
                    for (int np = 0; np < 2; np++) {
                        uint32_t b[4];
                        ldsm4t(b, smaddr(Us + (size_t)(kg + (lane & 15)) * (RBN + RPAD)
                                            + wn * 32 + np * 16 + ((lane >> 4) << 3)));
                        mma16816(acc[0][2 * np],     a[0], b[0], b[1]);
                        mma16816(acc[1][2 * np],     a[1], b[0], b[1]);
                        mma16816(acc[0][2 * np + 1], a[0], b[2], b[3]);
                        mma16816(acc[1][2 * np + 1], a[1], b[2], b[3]);
                    }
                }
                __syncthreads();
            }
        }

        // ---- epilogue: h_t = tanh(acc + XW_t), store bf16 ----
        #pragma unroll
        for (int mt = 0; mt < 2; mt++) {
            #pragma unroll
            for (int nt = 0; nt < 4; nt++) {
                int b0 = rowBase + wm * 32 + mt * 16 + (lane >> 2);
                int c  = colBase + wn * 32 + nt * 8 + (lane & 3) * 2;
                size_t i0 = ((size_t)b0 * SEQ + t) * UNITS + c;
                size_t i1 = ((size_t)(b0 + 8) * SEQ + t) * UNITS + c;
                float2 x0 = *(const float2*)(XW + i0);
                float2 x1 = *(const float2*)(XW + i1);
                float2 o0 = make_float2(tanhf(acc[mt][nt][0] + x0.x),
                                        tanhf(acc[mt][nt][1] + x0.y));
                float2 o1 = make_float2(tanhf(acc[mt][nt][2] + x1.x),
                                        tanhf(acc[mt][nt][3] + x1.y));
                *(__nv_bfloat162*)(X + i0) = __float22bfloat162_rn(o0);
                *(__nv_bfloat162*)(X + i1) = __float22bfloat162_rn(o1);
            }
        }

        // ---- row-group barrier (8 CTAs share this row of h) ----
        if (t < SEQ - 1) {
            __syncthreads();
            if (tid == 0) {
                unsigned* ctr = barRow + t;
                asm volatile("red.release.gpu.global.add.u32 [%0], %1;"
                             :: "l"(ctr), "r"(1u) : "memory");
                unsigned v;
                do {
                    asm volatile("ld.acquire.gpu.global.u32 %0, [%1];"
                                 : "=r"(v) : "l"(ctr) : "memory");
                } while (v < (unsigned)RGRIDX);
            }
            __syncthreads();
        }
    }
}

// ---------------- head: out[b] = sigmoid(h_last . Wo + bo) ----------------
__global__ void final_kernel(const __nv_bfloat16* __restrict__ X,
                             const float* __restrict__ Wo, const float* __restrict__ bo,
                             float* __restrict__ out) {
    int gw   = (blockIdx.x * blockDim.x + threadIdx.x) >> 5;
    int lane = threadIdx.x & 31;
    if (gw >= BATCH) return;
    const __nv_bfloat16* h = X + ((size_t)gw * SEQ + (SEQ - 1)) * UNITS;
    float s = 0.0f;
    for (int k = lane; k < UNITS; k += 32) s += __bfloat162float(h[k]) * Wo[k];
    #pragma unroll
    for (int o = 16; o; o >>= 1) s += __shfl_xor_sync(0xffffffffu, s, o);
    if (lane == 0) out[gw] = 1.0f / (1.0f + expf(-(s + bo[0])));
}

// ---------------- host ----------------
extern "C" void kernel_launch(void* const* d_in, const int* in_sizes, int n_in,
                              void* d_out, int out_size) {
    const int*   tokens = (const int*)d_in[0];
    const float* emb    = (const float*)d_in[1];
    const float* W[4]  = {(const float*)d_in[2], (const float*)d_in[5],
                          (const float*)d_in[8], (const float*)d_in[11]};
    const float* U[4]  = {(const float*)d_in[3], (const float*)d_in[6],
                          (const float*)d_in[9], (const float*)d_in[12]};
    const float* bv[4] = {(const float*)d_in[4], (const float*)d_in[7],
                          (const float*)d_in[10], (const float*)d_in[13]};
    const float* Wo = (const float*)d_in[14];
    const float* bo = (const float*)d_in[15];
    float* out = (float*)d_out;

    __nv_bfloat16 *X0p, *Xp, *W1bp, *Wbp, *Ubp;
    float* XWp;
    cudaGetSymbolAddress((void**)&X0p,  g_X0);
    cudaGetSymbolAddress((void**)&Xp,   g_X);
    cudaGetSymbolAddress((void**)&XWp,  g_XW);
    cudaGetSymbolAddress((void**)&W1bp, g_W1b);
    cudaGetSymbolAddress((void**)&Wbp,  g_Wb);
    cudaGetSymbolAddress((void**)&Ubp,  g_Ub);

    cudaFuncSetAttribute(rnn_layer_kernel,
                         cudaFuncAttributeMaxDynamicSharedMemorySize, RSMEM_BYTES);

    // weight conversions (cheap, deterministic, every call)
    padw1_kernel<<<(EMBP * UNITS + 255) / 256, 256>>>(W[0], W1bp);
    for (int l = 1; l < 4; l++)
        cvt_kernel<<<(UNITS * UNITS + 255) / 256, 256>>>(
            W[l], Wbp + (size_t)(l - 1) * UNITS * UNITS, UNITS * UNITS);
    for (int l = 0; l < 4; l++)
        cvt_kernel<<<(UNITS * UNITS + 255) / 256, 256>>>(
            U[l], Ubp + (size_t)l * UNITS * UNITS, UNITS * UNITS);

    // embedding gather (bf16, padded to EMBP) + barrier reset
    embed_kernel<<<(BT * EMBP + 255) / 256, 256>>>(tokens, emb, X0p);
    zero_bar_kernel<<<(4 * RGRIDY * SEQ + 255) / 256, 256>>>();

    for (int l = 0; l < 4; l++) {
        // parallel part: XW = X_in @ W_l + b_l over all B*T rows
        if (l == 0) {
            gemm_bf16<128><<<dim3(UNITS / 128, BT / 128), 256>>>(
                X0p, (long)EMBP, W1bp, EMBP, bv[0], XWp, (long)UNITS);
        } else {
            gemm_bf16<128><<<dim3(UNITS / 128, BT / 128), 256>>>(
                Xp, (long)UNITS, Wbp + (size_t)(l - 1) * UNITS * UNITS, UNITS, bv[l],
                XWp, (long)UNITS);
        }
        // sequential part: one persistent kernel runs all 80 steps
        rnn_layer_kernel<<<dim3(RGRIDX, RGRIDY), 256, RSMEM_BYTES>>>(
            Ubp + (size_t)l * UNITS * UNITS, XWp, Xp, l);
    }

    final_kernel<<<BATCH / 8, 256>>>(Xp, Wo, bo, out);
}

// round 7
// speedup vs baseline: 1.2938x; 1.0384x over previous
#include <cuda_runtime.h>
#include <cuda_bf16.h>
#include <cuda_fp16.h>
#include <cuda_fp8.h>
#include <cstdint>

#define VOCAB 10000
#define EMBD 100
#define EMBP 128          // EMB padded to one full 128B chunk
#define SEQ 80
#define UNITS 512
#define BATCH 2048
#define BT (BATCH*SEQ)    // 163840

// fp8 scaling: keep values out of e4m3 subnormal range
#define HSCALE 256.0f     // activations (|h|<=1 -> <=256 < 448 max)
#define WSCALE 64.0f      // weights (~0.02 -> ~1.3)
#define DESCALE (1.0f/(HSCALE*WSCALE))

#define RGRIDX 8          // column CTAs per row group
#define RGRIDY 16         // row groups

#define CH 128            // K bytes per chunk
#define AROW 144          // smem row pitch (128 + 16 pad -> conflict-free ldmatrix)
#define ABUF (128*AROW)   // 18432 B per chunk buffer
#define UROW 528          // U smem row pitch (512 + 16)
#define XW_SMEM (6*ABUF)              // 3 A + 3 B buffers = 110592
#define R_SMEM (64*UROW + 4*ABUF)     // 33792 + 73728 = 107520

// ---------------- device scratch (static, no allocations); t-major rows ----------------
__device__ __align__(16) uint8_t        g_X0[(size_t)BT * EMBP];   // embedded input, fp8*HSCALE
__device__ __align__(16) uint8_t        g_X [(size_t)BT * UNITS];  // h, fp8*HSCALE
__device__ __align__(16) __nv_bfloat16  g_XW[(size_t)BT * UNITS];  // input projection, bf16
__device__ __align__(16) uint8_t        g_W1t[UNITS * EMBP];       // W1^T [n][k] fp8*WSCALE
__device__ __align__(16) uint8_t        g_Wt [3][UNITS * UNITS];   // W2..4^T
__device__ __align__(16) uint8_t        g_Ut [4][UNITS * UNITS];   // U1..4^T
__device__ unsigned g_bar[4][RGRIDY][SEQ];                         // inter-CTA step barriers

// ---------------- PTX helpers ----------------
__device__ __forceinline__ uint32_t smaddr(const void* p) {
    return (uint32_t)__cvta_generic_to_shared(p);
}
__device__ __forceinline__ void cpa16(uint32_t dst, const void* src) {
    asm volatile("cp.async.cg.shared.global [%0], [%1], 16;\n" :: "r"(dst), "l"(src));
}
__device__ __forceinline__ void cp_commit() { asm volatile("cp.async.commit_group;\n"); }
template<int N> __device__ __forceinline__ void cp_wait() {
    asm volatile("cp.async.wait_group %0;\n" :: "n"(N));
}
__device__ __forceinline__ void ldsm4(uint32_t (&r)[4], uint32_t addr) {
    asm volatile("ldmatrix.sync.aligned.m8n8.x4.shared.b16 {%0,%1,%2,%3}, [%4];\n"
                 : "=r"(r[0]), "=r"(r[1]), "=r"(r[2]), "=r"(r[3]) : "r"(addr));
}
// fp8 e4m3 MMA, fp32 accum. Fragment bytes == bf16 m16n8k16 fragments reinterpreted,
// so non-trans ldmatrix on k-contiguous layouts (A row-major, B n-major) feeds it directly.
__device__ __forceinline__ void mma_fp8(float (&d)[4], const uint32_t (&a)[4],
                                        uint32_t b0, uint32_t b1) {
    asm volatile("mma.sync.aligned.m16n8k32.row.col.f32.e4m3.e4m3.f32 "
                 "{%0,%1,%2,%3}, {%4,%5,%6,%7}, {%8,%9}, {%0,%1,%2,%3};\n"
                 : "+f"(d[0]), "+f"(d[1]), "+f"(d[2]), "+f"(d[3])
                 : "r"(a[0]), "r"(a[1]), "r"(a[2]), "r"(a[3]), "r"(b0), "r"(b1));
}
__device__ __forceinline__ uint8_t to_fp8(float v) {
    return (uint8_t)__nv_cvt_float_to_fp8(v, __NV_SATFINITE, __NV_E4M3);
}

// ---------------- small helper kernels ----------------
__global__ void cvtT_fp8(const float* __restrict__ s, uint8_t* __restrict__ d,
                         int K, int Kp) {
    // s: [K][UNITS] fp32 -> d: [UNITS][Kp] fp8 (transposed, scaled, zero-padded)
    int i = blockIdx.x * blockDim.x + threadIdx.x;
    if (i >= UNITS * Kp) return;
    int n = i / Kp, k = i - n * Kp;
    float v = (k < K) ? s[(size_t)k * UNITS + n] * WSCALE : 0.0f;
    d[i] = to_fp8(v);
}

__global__ void embed_fp8(const int* __restrict__ tokens, const float* __restrict__ emb,
                          uint8_t* __restrict__ X0) {
    int i = blockIdx.x * blockDim.x + threadIdx.x;
    if (i >= BT * EMBP) return;
    int r = i / EMBP, k = i - r * EMBP;
    int t = r / BATCH, b = r - t * BATCH;
    float v = (k < EMBD) ? emb[(size_t)tokens[b * SEQ + t] * EMBD + k] * HSCALE : 0.0f;
    X0[i] = to_fp8(v);
}

__global__ void zero_bar_kernel() {
    int i = blockIdx.x * blockDim.x + threadIdx.x;
    if (i < 4 * RGRIDY * SEQ) ((unsigned*)g_bar)[i] = 0u;
}

// ================= XW GEMM (fp8): C[M,N] = (A @ Bt^T)*DESCALE + bias, bf16 out =================
// CTA tile M=128 N=128, 8 warps (4 M x 2 N, each 32x64). 3-buffer/depth-2 cp.async ring.
__global__ __launch_bounds__(256, 1) void gemm_fp8(
    const uint8_t* __restrict__ A, int lda,
    const uint8_t* __restrict__ Bt, int ldb,
    const float* __restrict__ bias,
    __nv_bfloat16* __restrict__ C, int nchunk)
{
    extern __shared__ __align__(128) uint8_t smbuf[];
    const uint32_t sb = smaddr(smbuf);
    const uint32_t BOFF = 3 * ABUF;

    const int tid = threadIdx.x, lane = tid & 31, wid = tid >> 5;
    const int wm = wid & 3, wn = wid >> 2;
    const int rowBase = blockIdx.y * 128, colBase = blockIdx.x * 128;

    auto loadAB = [&](int c) {
        const int buf = c % 3;
        const uint8_t* Ab = A  + (size_t)rowBase * lda + c * CH;
        const uint8_t* Bb = Bt + (size_t)colBase * ldb + c * CH;
        #pragma unroll
        for (int i = 0; i < 4; i++) {
            int u = tid + i * 256;
            int row = u >> 3, c16 = (u & 7) * 16;
            cpa16(sb + buf * ABUF + row * AROW + c16, Ab + (size_t)row * lda + c16);
            cpa16(sb + BOFF + buf * ABUF + row * AROW + c16, Bb + (size_t)row * ldb + c16);
        }
        cp_commit();
    };

    loadAB(0);
    if (nchunk > 1) loadAB(1);

    float acc[2][8][4];
    #pragma unroll
    for (int mt = 0; mt < 2; mt++)
        #pragma unroll
        for (int nf = 0; nf < 8; nf++)
            #pragma unroll
            for (int j = 0; j < 4; j++) acc[mt][nf][j] = 0.0f;

    for (int c = 0; c < nchunk; ++c) {
        if (c + 1 < nchunk) cp_wait<1>(); else cp_wait<0>();
        __syncthreads();
        if (c + 2 < nchunk) loadAB(c + 2);     // overlaps mma below
        const uint32_t sa  = sb + (c % 3) * ABUF;
        const uint32_t sbb = sb + BOFF + (c % 3) * ABUF;
        #pragma unroll
        for (int k = 0; k < 4; k++) {          // 4 x k32 per chunk
            uint32_t a[2][4];
            #pragma unroll
            for (int mt = 0; mt < 2; mt++)
                ldsm4(a[mt], sa + (uint32_t)(wm * 32 + mt * 16 + (lane & 15)) * AROW
                                + k * 32 + ((lane >> 4) << 4));
            #pragma unroll
            for (int g = 0; g < 4; g++) {      // 4 n16 groups over N64
                uint32_t b[4];
                ldsm4(b, sbb + (uint32_t)(wn * 64 + g * 16 + (lane & 7)
                                          + ((lane >> 4) << 3)) * AROW
                             + k * 32 + (((lane >> 3) & 1) << 4));
                mma_fp8(acc[0][2 * g],     a[0], b[0], b[1]);
                mma_fp8(acc[1][2 * g],     a[1], b[0], b[1]);
                mma_fp8(acc[0][2 * g + 1], a[0], b[2], b[3]);
                mma_fp8(acc[1][2 * g + 1], a[1], b[2], b[3]);
            }
        }
    }

    const int r0 = rowBase + wm * 32 + (lane >> 2);
    const int c0 = colBase + wn * 64 + (lane & 3) * 2;
    #pragma unroll
    for (int mt = 0; mt < 2; mt++)
        #pragma unroll
        for (int nf = 0; nf < 8; nf++) {
            int r = r0 + mt * 16, c = c0 + nf * 8;
            float b0 = bias[c], b1 = bias[c + 1];
            __nv_bfloat162 v0 = __float22bfloat162_rn(
                make_float2(acc[mt][nf][0] * DESCALE + b0, acc[mt][nf][1] * DESCALE + b1));
            __nv_bfloat162 v1 = __float22bfloat162_rn(
                make_float2(acc[mt][nf][2] * DESCALE + b0, acc[mt][nf][3] * DESCALE + b1));
            *(__nv_bfloat162*)(C + (size_t)r * UNITS + c)       = v0;
            *(__nv_bfloat162*)(C + (size_t)(r + 8) * UNITS + c) = v1;
        }
}

// ================= persistent recurrence (fp8) =================
// grid (8,16) = 128 CTAs, 1/SM, all co-resident. CTA (x,y): rows [128y..), cols [64x..).
// U slice [64 n][512 k] resident in SMEM. Per step: 4 A-chunks issued up-front (4 groups),
// consumed with progressive wait_group so loads stream under mma.
__global__ __launch_bounds__(256, 1) void rnn_fp8(
    const uint8_t* __restrict__ Ut,
    const __nv_bfloat16* __restrict__ XW,
    uint8_t* __restrict__ X,
    int layer)
{
    extern __shared__ __align__(128) uint8_t smbuf[];
    const uint32_t sb = smaddr(smbuf);
    const uint32_t AOFF = 64 * UROW;

    const int tid = threadIdx.x, lane = tid & 31, wid = tid >> 5;
    const int wm = wid & 3, wn = wid >> 2;
    const int rowBase = blockIdx.y * 128, colBase = blockIdx.x * 64;

    // resident U slice [64 n][512 k]
    #pragma unroll
    for (int i = 0; i < 8; i++) {
        int u = tid + i * 256;
        int row = u >> 5, c16 = (u & 31) * 16;
        cpa16(sb + (uint32_t)row * UROW + c16, Ut + (size_t)(colBase + row) * UNITS + c16);
    }
    cp_commit();
    cp_wait<0>();
    __syncthreads();

    unsigned* barRow = &g_bar[layer][blockIdx.y][0];
    const int r0 = rowBase + wm * 32 + (lane >> 2);
    const int c0 = colBase + wn * 32 + (lane & 3) * 2;

    for (int t = 0; t < SEQ; ++t) {
        if (t > 0) {
            // issue all 4 A-chunk loads (h_{t-1}) immediately: 4 commit groups
            const uint8_t* Ab = X + ((size_t)(t - 1) * BATCH + rowBase) * UNITS;
            #pragma unroll
            for (int c = 0; c < 4; c++) {
                #pragma unroll
                for (int i = 0; i < 4; i++) {
                    int u = tid + i * 256;
                    int row = u >> 3, c16 = (u & 7) * 16;
                    cpa16(sb + AOFF + c * ABUF + (uint32_t)row * AROW + c16,
                          Ab + (size_t)row * UNITS + c * CH + c16);
                }
                cp_commit();
            }
        }

        // prefetch XW fragments (independent of the inter-CTA barrier)
        uint32_t xwv[2][4][2];
        #pragma unroll
        for (int mt = 0; mt < 2; mt++)
            #pragma unroll
            for (int nf = 0; nf < 4; nf++) {
                size_t base = ((size_t)t * BATCH + r0 + mt * 16) * UNITS + c0 + nf * 8;
                xwv[mt][nf][0] = *(const uint32_t*)(XW + base);
                xwv[mt][nf][1] = *(const uint32_t*)(XW + base + 8 * UNITS);
            }

        float acc[2][4][4];
        #pragma unroll
        for (int mt = 0; mt < 2; mt++)
            #pragma unroll
            for (int nf = 0; nf < 4; nf++)
                #pragma unroll
                for (int j = 0; j < 4; j++) acc[mt][nf][j] = 0.0f;

        if (t > 0) {
            #pragma unroll
            for (int c = 0; c < 4; c++) {
                if (c == 0)      cp_wait<3>();
                else if (c == 1) cp_wait<2>();
                else if (c == 2) cp_wait<1>();
                else             cp_wait<0>();
                __syncthreads();
                const uint32_t sa = sb + AOFF + c * ABUF;
                #pragma unroll
                for (int k = 0; k < 4; k++) {
                    uint32_t a[2][4];
                    #pragma unroll
                    for (int mt = 0; mt < 2; mt++)
                        ldsm4(a[mt], sa + (uint32_t)(wm * 32 + mt * 16 + (lane & 15)) * AROW
                                        + k * 32 + ((lane >> 4) << 4));
                    #pragma unroll
                    for (int g = 0; g < 2; g++) {
                        uint32_t b[4];
                        ldsm4(b, sb + (uint32_t)(wn * 32 + g * 16 + (lane & 7)
                                                 + ((lane >> 4) << 3)) * UROW
                                    + c * CH + k * 32 + (((lane >> 3) & 1) << 4));
                        mma_fp8(acc[0][2 * g],     a[0], b[0], b[1]);
                        mma_fp8(acc[1][2 * g],     a[1], b[0], b[1]);
                        mma_fp8(acc[0][2 * g + 1], a[0], b[2], b[3]);
                        mma_fp8(acc[1][2 * g + 1], a[1], b[2], b[3]);
                    }
                }
            }
        }

        // epilogue: h = tanh(acc*DESCALE + XW); store fp8*HSCALE
        #pragma unroll
        for (int mt = 0; mt < 2; mt++)
            #pragma unroll
            for (int nf = 0; nf < 4; nf++) {
                float2 xa = __bfloat1622float2(*(__nv_bfloat162*)&xwv[mt][nf][0]);
                float2 xb = __bfloat1622float2(*(__nv_bfloat162*)&xwv[mt][nf][1]);
                float p0 = tanhf(acc[mt][nf][0] * DESCALE + xa.x);
                float p1 = tanhf(acc[mt][nf][1] * DESCALE + xa.y);
                float p2 = tanhf(acc[mt][nf][2] * DESCALE + xb.x);
                float p3 = tanhf(acc[mt][nf][3] * DESCALE + xb.y);
                size_t base = ((size_t)t * BATCH + r0 + mt * 16) * UNITS + c0 + nf * 8;
                *(unsigned short*)(X + base) =
                    __nv_cvt_float2_to_fp8x2(make_float2(p0 * HSCALE, p1 * HSCALE),
                                             __NV_SATFINITE, __NV_E4M3);
                *(unsigned short*)(X + base + 8 * UNITS) =
                    __nv_cvt_float2_to_fp8x2(make_float2(p2 * HSCALE, p3 * HSCALE),
                                             __NV_SATFINITE, __NV_E4M3);
            }

        // inter-CTA barrier: the 8 column-CTAs sharing this row group
        if (t < SEQ - 1) {
            __syncthreads();
            if (tid == 0) {
                unsigned* ctr = barRow + t;
                asm volatile("red.release.gpu.global.add.u32 [%0], %1;"
                             :: "l"(ctr), "r"(1u) : "memory");
                unsigned v;
                do {
                    asm volatile("ld.acquire.gpu.global.u32 %0, [%1];"
                                 : "=r"(v) : "l"(ctr) : "memory");
                } while (v < (unsigned)RGRIDX);
            }
            __syncthreads();
        }
    }
}

// ---------------- head: out[b] = sigmoid(h_last . Wo + bo) ----------------
__global__ void final_kernel(const uint8_t* __restrict__ X,
                             const float* __restrict__ Wo, const float* __restrict__ bo,
                             float* __restrict__ out) {
    int gw   = (blockIdx.x * blockDim.x + threadIdx.x) >> 5;
    int lane = threadIdx.x & 31;
    if (gw >= BATCH) return;
    const uint8_t* h = X + ((size_t)(SEQ - 1) * BATCH + gw) * UNITS;
    float s = 0.0f;
    for (int k = lane; k < UNITS; k += 32) {
        __half_raw hr = __nv_cvt_fp8_to_halfraw(h[k], __NV_E4M3);
        s += __half2float(*(__half*)&hr) * Wo[k];
    }
    #pragma unroll
    for (int o = 16; o; o >>= 1) s += __shfl_xor_sync(0xffffffffu, s, o);
    if (lane == 0) out[gw] = 1.0f / (1.0f + expf(-(s * (1.0f / HSCALE) + bo[0])));
}

// ---------------- host ----------------
extern "C" void kernel_launch(void* const* d_in, const int* in_sizes, int n_in,
                              void* d_out, int out_size) {
    const int*   tokens = (const int*)d_in[0];
    const float* emb    = (const float*)d_in[1];
    const float* W[4]  = {(const float*)d_in[2], (const float*)d_in[5],
                          (const float*)d_in[8], (const float*)d_in[11]};
    const float* U[4]  = {(const float*)d_in[3], (const float*)d_in[6],
                          (const float*)d_in[9], (const float*)d_in[12]};
    const float* bv[4] = {(const float*)d_in[4], (const float*)d_in[7],
                          (const float*)d_in[10], (const float*)d_in[13]};
    const float* Wo = (const float*)d_in[14];
    const float* bo = (const float*)d_in[15];
    float* out = (float*)d_out;

    uint8_t *X0p, *Xp, *W1tp, *Wtp, *Utp;
    __nv_bfloat16* XWp;
    cudaGetSymbolAddress((void**)&X0p,  g_X0);
    cudaGetSymbolAddress((void**)&Xp,   g_X);
    cudaGetSymbolAddress((void**)&XWp,  g_XW);
    cudaGetSymbolAddress((void**)&W1tp, g_W1t);
    cudaGetSymbolAddress((void**)&Wtp,  g_Wt);
    cudaGetSymbolAddress((void**)&Utp,  g_Ut);

    cudaFuncSetAttribute(gemm_fp8, cudaFuncAttributeMaxDynamicSharedMemorySize, XW_SMEM);
    cudaFuncSetAttribute(rnn_fp8,  cudaFuncAttributeMaxDynamicSharedMemorySize, R_SMEM);

    // weight conversions (transpose + scale to fp8)
    cvtT_fp8<<<(UNITS * EMBP + 255) / 256, 256>>>(W[0], W1tp, EMBD, EMBP);
    for (int l = 1; l < 4; l++)
        cvtT_fp8<<<(UNITS * UNITS + 255) / 256, 256>>>(
            W[l], Wtp + (size_t)(l - 1) * UNITS * UNITS, UNITS, UNITS);
    for (int l = 0; l < 4; l++)
        cvtT_fp8<<<(UNITS * UNITS + 255) / 256, 256>>>(
            U[l], Utp + (size_t)l * UNITS * UNITS, UNITS, UNITS);

    embed_fp8<<<(BT * EMBP + 255) / 256, 256>>>(tokens, emb, X0p);
    zero_bar_kernel<<<(4 * RGRIDY * SEQ + 255) / 256, 256>>>();

    for (int l = 0; l < 4; l++) {
        if (l == 0) {
            gemm_fp8<<<dim3(UNITS / 128, BT / 128), 256, XW_SMEM>>>(
                X0p, EMBP, W1tp, EMBP, bv[0], XWp, 1);
        } else {
            gemm_fp8<<<dim3(UNITS / 128, BT / 128), 256, XW_SMEM>>>(
                Xp, UNITS, Wtp + (size_t)(l - 1) * UNITS * UNITS, UNITS,
                bv[l], XWp, 4);
        }
        rnn_fp8<<<dim3(RGRIDX, RGRIDY), 256, R_SMEM>>>(
            Utp + (size_t)l * UNITS * UNITS, XWp, Xp, l);
    }

    final_kernel<<<BATCH / 8, 256>>>(Xp, Wo, bo, out);
}